// round 15
// baseline (speedup 1.0000x reference)
#include <cuda_runtime.h>
#include <math.h>
#include <stdint.h>

#define C 128
#define Kc 7
#define TILE 64
#define RST 136            // xs row stride in u32 (136 mod 32 == 8 -> conflict-free)
#define DEPTH 16
#define Bz 4
#define S0 8192

// ---------------- scratch (no allocs allowed) ----------------
__device__ float g_bufA[Bz * S0 * C];
__device__ float g_bufB[Bz * S0 * C];
// dyn weights, MMA-native: [i][k][half(0..7)][d(0..127)][g(0..3)][4 u32: bh0,bh1,bl0,bl1]
__device__ unsigned g_whl[DEPTH * Kc * 8 * 128 * 16];
// pointwise, same per-half layout: [i][half][d][g][4]
__device__ unsigned g_phl[DEPTH * 8 * 128 * 16];
__device__ float g_zf[Bz * 4000];

// tanh(x) = 1 - 2/(1 + e^{2x})  (exact constants; RCP+FFMA form)
__device__ __forceinline__ float fast_tanh(float x) {
    float e = __expf(2.0f * x);
    float r = __frcp_rn(1.0f + e);
    return fmaf(-2.0f, r, 1.0f);
}
// round-7 proven gelu
__device__ __forceinline__ float gelu_t(float x) {
    float u = 0.7978845608028654f * (x + 0.044715f * x * x * x);
    return __fdividef(x, 1.0f + __expf(-2.0f * u));
}
__device__ __forceinline__ unsigned pk2(float x0, float x1) {
    unsigned r; asm("cvt.rn.bf16x2.f32 %0, %1, %2;" : "=r"(r) : "f"(x1), "f"(x0)); return r;
}
__device__ __forceinline__ float bf_lo(unsigned u) { return __uint_as_float(u << 16); }
__device__ __forceinline__ float bf_hi(unsigned u) { return __uint_as_float(u & 0xffff0000u); }

#define MMA16(d, a, b0v, b1v) asm volatile( \
    "mma.sync.aligned.m16n8k16.row.col.f32.bf16.bf16.f32 " \
    "{%0,%1,%2,%3},{%4,%5,%6,%7},{%8,%9},{%0,%1,%2,%3};" \
    : "+f"(d[0]), "+f"(d[1]), "+f"(d[2]), "+f"(d[3]) \
    : "r"(a[0]), "r"(a[1]), "r"(a[2]), "r"(a[3]), "r"(b0v), "r"(b1v))

// ---------------- prep: w_dyn [i][d][c][k] -> bf16 hi/lo MMA layout ----------------
__global__ void split_wd_kernel(const float* __restrict__ w, uint4* __restrict__ o) {
    int idx = blockIdx.x * blockDim.x + threadIdx.x;   // over (i,k,half,d,g)
    if (idx >= DEPTH * Kc * 8 * 128 * 4) return;
    int g = idx & 3;
    int d = (idx >> 2) & 127;
    int half = (idx >> 9) & 7;
    int rest = idx >> 12;
    int k = rest % Kc;
    int i = rest / Kc;
    int c0 = half * 16 + 2 * g;
    const float* wb = w + ((size_t)(i * C + d) * C) * Kc + k;
    float v0 = wb[(size_t)c0 * Kc],       v1 = wb[(size_t)(c0 + 1) * Kc];
    float v8 = wb[(size_t)(c0 + 8) * Kc], v9 = wb[(size_t)(c0 + 9) * Kc];
    unsigned h0 = pk2(v0, v1), h1 = pk2(v8, v9);
    unsigned l0 = pk2(v0 - bf_lo(h0), v1 - bf_hi(h0));
    unsigned l1 = pk2(v8 - bf_lo(h1), v9 - bf_hi(h1));
    o[idx] = make_uint4(h0, h1, l0, l1);
}

__global__ void split_pk_kernel(const float* __restrict__ p, uint4* __restrict__ o) {
    int idx = blockIdx.x * blockDim.x + threadIdx.x;   // over (i,half,d,g)
    if (idx >= DEPTH * 8 * 128 * 4) return;
    int g = idx & 3;
    int d = (idx >> 2) & 127;
    int half = (idx >> 9) & 7;
    int i = idx >> 12;
    int c0 = half * 16 + 2 * g;
    const float* pb = p + (size_t)i * C * C + d;
    float v0 = pb[(size_t)c0 * C],       v1 = pb[(size_t)(c0 + 1) * C];
    float v8 = pb[(size_t)(c0 + 8) * C], v9 = pb[(size_t)(c0 + 9) * C];
    unsigned h0 = pk2(v0, v1), h1 = pk2(v8, v9);
    unsigned l0 = pk2(v0 - bf_lo(h0), v1 - bf_hi(h0));
    unsigned l1 = pk2(v8 - bf_lo(h1), v9 - bf_hi(h1));
    o[idx] = make_uint4(h0, h1, l0, l1);
}

// ---------------- start: z = gelu(ipt @ start_k + start_b) ----------------
__global__ void start_kernel(const float* __restrict__ ipt, const float* __restrict__ sk,
                             const float* __restrict__ sb, float* __restrict__ z) {
    int idx = blockIdx.x * blockDim.x + threadIdx.x;
    int c = idx & (C - 1);
    int bt = idx >> 7;
    z[idx] = gelu_t(ipt[bt] * sk[c] + sb[c]);
}

// ---------------- fused conv block, bf16x3, 3-stage single-sync pipeline ----------------
// Round-6 geometry: 256 threads = 8 warps, TILE=64, warp = 16 rows x 64 cols, 2 CTAs/SM.
// 3-stage cp.async ring: at chunk q, wait_group<=1 makes chunk q resident, ONE barrier
// publishes it and retires readers of the stage chunk q+2 will overwrite.
template <int NS>
__global__ __launch_bounds__(256, 2) void conv_tpl(
    const float* __restrict__ xin, float* __restrict__ xout,
    int T_in, int T_out,
    const unsigned* __restrict__ wsp,   // layer's [Kc][8][128][16] u32
    const float* __restrict__ ls, const float* __restrict__ lb,
    const unsigned* __restrict__ pks,   // layer's [8][128][16] u32
    const float* __restrict__ pb) {
    constexpr int XROWS = (NS == 1) ? (TILE + 6) : (2 * TILE + 12);
    constexpr int CPB   = (NS == 1) ? 32 : 16;        // channels per chunk
    constexpr int HPC   = CPB / 16;                   // halves per chunk (2 / 1)
    constexpr int NCPP  = C / CPB;                    // chunks per pass (4 / 8)
    constexpr int NWCH  = NS * Kc * NCPP;             // 28 / 112
    constexpr int NCH   = NWCH + NCPP;
    constexpr int CHU   = HPC * 2048;                 // u32 per chunk
    constexpr int NCPA  = HPC * 2;                    // 16B cp.asyncs per thread

    extern __shared__ unsigned smu[];
    unsigned* xs   = smu;                    // XROWS * RST (rows 0..63 reused for LN output)
    unsigned* wbuf = smu + XROWS * RST;      // 3 * CHU
    float* lnS = (float*)(wbuf + 3 * CHU);   // [2][64]
    float* lnQ = lnS + 128;
    float* prm = lnQ + 128;                  // ls | lb | pb

    const int b  = blockIdx.y;
    const int t0 = blockIdx.x * TILE;
    const float* xb = xin + (size_t)b * T_in * C;
    float* ob = xout + (size_t)b * T_out * C;

    const int tid  = threadIdx.x;
    const int lane = tid & 31;
    const int wid  = tid >> 5;
    const int wm   = wid & 3;
    const int wn   = wid >> 2;
    const int gr   = lane >> 2;
    const int gq   = lane & 3;

    if (tid < 128) { prm[tid] = ls[tid]; prm[128 + tid] = lb[tid]; prm[256 + tid] = pb[tid]; }

    // load x rows, convert+pack bf16 hi/lo
    for (int i = tid; i < XROWS * 32; i += 256) {
        int r = i >> 5, c4 = i & 31;
        int rr = min(NS * t0 + r, T_in - 1);
        float4 v = ((const float4*)(xb + (size_t)rr * C))[c4];
        unsigned h0 = pk2(v.x, v.y);
        unsigned l0 = pk2(v.x - bf_lo(h0), v.y - bf_hi(h0));
        unsigned h1 = pk2(v.z, v.w);
        unsigned l1 = pk2(v.z - bf_lo(h1), v.w - bf_hi(h1));
        *(uint4*)&xs[r * RST + c4 * 4] = make_uint4(h0, l0, h1, l1);
    }

    const int row0 = 16 * wm + gr;
    const int row1 = row0 + 8;

    const unsigned wsh = (unsigned)__cvta_generic_to_shared(wbuf);
    const int wOff = (wn * 64 + gr) * 16 + gq * 4;

    // chunk q -> global source pointer
    auto chunk_src = [&](int q) -> const unsigned* {
        if (q >= NWCH) return pks + (size_t)(q - NWCH) * CHU;
        if (NS == 1) return wsp + (size_t)q * CHU;     // contiguous (k,cp) stream
        // NS==2: k = q>>4, cp = q&7 (each k streamed twice, s = (q>>3)&1)
        return wsp + (size_t)(((q >> 4) * 8 + (q & 7))) * 2048;
    };
    auto prefetch = [&](int q) {
        const unsigned* src = chunk_src(q);
        unsigned da = wsh + (unsigned)((q % 3) * (CHU * 4)) + tid * 16;
        const unsigned* sp = src + tid * 4;
#pragma unroll
        for (int j = 0; j < NCPA; j++)
            asm volatile("cp.async.cg.shared.global [%0], [%1], 16;"
                         :: "r"(da + j * 4096), "l"(sp + j * 1024));
    };

    float Y[8][4], G[8][4];
#pragma unroll
    for (int j = 0; j < 8; j++) { Y[j][0] = Y[j][1] = Y[j][2] = Y[j][3] = 0.0f; }

    // prologue: 2 chunks in flight (sync covers xs/prm stores before first compute)
    prefetch(0);
    asm volatile("cp.async.commit_group;");
    prefetch(1);
    asm volatile("cp.async.commit_group;");

    for (int q = 0; q < NCH; q++) {
        asm volatile("cp.async.wait_group 1;");   // chunk q resident (q+1 may be in flight)
        __syncthreads();                          // publish chunk q; retire readers of stage (q+2)%3
        if (q + 2 < NCH) prefetch(q + 2);
        asm volatile("cp.async.commit_group;");   // uniform group pacing (empty ok)

        const unsigned* wb = wbuf + (q % 3) * CHU;
        const bool wphase = (q < NWCH);
        int k = 0, s = 0, cp, arow0, arow1;
        if (wphase) {
            cp = q & (NCPP - 1);
            if (NS == 1) { k = q >> 2; arow0 = row0 + 6; arow1 = row1 + 6; }
            else { k = q >> 4; s = (q >> 3) & 1; arow0 = 2 * row0 + 12 + s; arow1 = 2 * row1 + 12 + s; }
            if (cp == 0) {
#pragma unroll
                for (int j = 0; j < 8; j++) { G[j][0] = G[j][1] = G[j][2] = G[j][3] = 0.0f; }
            }
        } else {
            cp = q - NWCH;
            arow0 = row0; arow1 = row1;
            if (q == NWCH) {
#pragma unroll
                for (int j = 0; j < 8; j++) { G[j][0] = G[j][1] = G[j][2] = G[j][3] = 0.0f; }
            }
        }
        const int cb = cp * CPB;

#pragma unroll
        for (int h = 0; h < HPC; h++) {
            int c2b = (cb >> 1) + h * 8;        // c2 base of this 16-chan half
            uint2 p0 = *(const uint2*)&xs[arow0 * RST + (c2b + gq) * 2];
            uint2 p1 = *(const uint2*)&xs[arow1 * RST + (c2b + gq) * 2];
            uint2 p2 = *(const uint2*)&xs[arow0 * RST + (c2b + gq + 4) * 2];
            uint2 p3 = *(const uint2*)&xs[arow1 * RST + (c2b + gq + 4) * 2];
            unsigned ah[4] = { p0.x, p1.x, p2.x, p3.x };
            unsigned al[4] = { p0.y, p1.y, p2.y, p3.y };
            const unsigned* wh = wb + h * 2048 + wOff;
#pragma unroll
            for (int j = 0; j < 8; j++) {
                uint4 bv = *(const uint4*)(wh + j * 128);
                MMA16(G[j], ah, bv.x, bv.y);
                MMA16(G[j], ah, bv.z, bv.w);
                MMA16(G[j], al, bv.x, bv.y);
            }
        }

        if (wphase && cp == NCPP - 1) {
            // fold tap (k[,s]): Y += x[tap,d] * tanh(G)
            int f0 = (NS == 1) ? (row0 + k) : (2 * row0 + 2 * k + s);
            int f1 = (NS == 1) ? (f0 + 8) : (f0 + 16);
#pragma unroll
            for (int j = 0; j < 8; j++) {
                int c2 = wn * 32 + j * 4 + gq;
                uint2 u0 = *(const uint2*)&xs[f0 * RST + c2 * 2];
                uint2 u1 = *(const uint2*)&xs[f1 * RST + c2 * 2];
                Y[j][0] += (bf_lo(u0.x) + bf_lo(u0.y)) * fast_tanh(G[j][0]);
                Y[j][1] += (bf_hi(u0.x) + bf_hi(u0.y)) * fast_tanh(G[j][1]);
                Y[j][2] += (bf_lo(u1.x) + bf_lo(u1.y)) * fast_tanh(G[j][2]);
                Y[j][3] += (bf_hi(u1.x) + bf_hi(u1.y)) * fast_tanh(G[j][3]);
            }
            if (q == NWCH - 1) {
                // residual + layernorm; internal barrier orders all xs reads before rewrite
                int r0 = (NS == 1) ? (row0 + 6) : (2 * row0 + 12);
                int r1 = (NS == 1) ? (r0 + 8) : (r0 + 16);
                float s0 = 0, q0 = 0, s1 = 0, q1 = 0;
#pragma unroll
                for (int j = 0; j < 8; j++) {
                    int c2 = wn * 32 + j * 4 + gq;
                    uint2 u0 = *(const uint2*)&xs[r0 * RST + c2 * 2];
                    uint2 u1 = *(const uint2*)&xs[r1 * RST + c2 * 2];
                    Y[j][0] += bf_lo(u0.x) + bf_lo(u0.y);
                    Y[j][1] += bf_hi(u0.x) + bf_hi(u0.y);
                    Y[j][2] += bf_lo(u1.x) + bf_lo(u1.y);
                    Y[j][3] += bf_hi(u1.x) + bf_hi(u1.y);
                    s0 += Y[j][0] + Y[j][1]; q0 += Y[j][0] * Y[j][0] + Y[j][1] * Y[j][1];
                    s1 += Y[j][2] + Y[j][3]; q1 += Y[j][2] * Y[j][2] + Y[j][3] * Y[j][3];
                }
#pragma unroll
                for (int o = 1; o <= 2; o <<= 1) {
                    s0 += __shfl_xor_sync(0xffffffffu, s0, o);
                    q0 += __shfl_xor_sync(0xffffffffu, q0, o);
                    s1 += __shfl_xor_sync(0xffffffffu, s1, o);
                    q1 += __shfl_xor_sync(0xffffffffu, q1, o);
                }
                if (gq == 0) {
                    lnS[wn * 64 + row0] = s0; lnQ[wn * 64 + row0] = q0;
                    lnS[wn * 64 + row1] = s1; lnQ[wn * 64 + row1] = q1;
                }
                __syncthreads();
                float Sa = lnS[row0] + lnS[64 + row0], Qa = lnQ[row0] + lnQ[64 + row0];
                float Sb = lnS[row1] + lnS[64 + row1], Qb = lnQ[row1] + lnQ[64 + row1];
                float m0 = Sa * (1.0f / C), m1 = Sb * (1.0f / C);
                float i0 = rsqrtf(fmaxf(Qa * (1.0f / C) - m0 * m0, 0.0f) + 1e-6f);
                float i1 = rsqrtf(fmaxf(Qb * (1.0f / C) - m1 * m1, 0.0f) + 1e-6f);
#pragma unroll
                for (int j = 0; j < 8; j++) {
                    int col = wn * 64 + j * 8 + gq * 2;
                    Y[j][0] = (Y[j][0] - m0) * i0 * prm[col]     + prm[128 + col];
                    Y[j][1] = (Y[j][1] - m0) * i0 * prm[col + 1] + prm[128 + col + 1];
                    Y[j][2] = (Y[j][2] - m1) * i1 * prm[col]     + prm[128 + col];
                    Y[j][3] = (Y[j][3] - m1) * i1 * prm[col + 1] + prm[128 + col + 1];
                    int c2 = col >> 1;
                    unsigned h0 = pk2(Y[j][0], Y[j][1]);
                    unsigned l0 = pk2(Y[j][0] - bf_lo(h0), Y[j][1] - bf_hi(h0));
                    unsigned h1 = pk2(Y[j][2], Y[j][3]);
                    unsigned l1 = pk2(Y[j][2] - bf_lo(h1), Y[j][3] - bf_hi(h1));
                    *(uint2*)&xs[row0 * RST + c2 * 2] = make_uint2(h0, l0);
                    *(uint2*)&xs[row1 * RST + c2 * 2] = make_uint2(h1, l1);
                }
                // next loop-top __syncthreads publishes LN rows before pw A-loads
            }
        }
    }

    // epilogue: out = y_ln + gelu(G + pb)
#pragma unroll
    for (int j = 0; j < 8; j++) {
        int col = wn * 64 + j * 8 + gq * 2;
        int tg0 = t0 + row0, tg1 = t0 + row1;
        float o0 = Y[j][0] + gelu_t(G[j][0] + prm[256 + col]);
        float o1 = Y[j][1] + gelu_t(G[j][1] + prm[256 + col + 1]);
        float o2 = Y[j][2] + gelu_t(G[j][2] + prm[256 + col]);
        float o3 = Y[j][3] + gelu_t(G[j][3] + prm[256 + col + 1]);
        if (tg0 < T_out) *(float2*)&ob[(size_t)tg0 * C + col] = make_float2(o0, o1);
        if (tg1 < T_out) *(float2*)&ob[(size_t)tg1 * C + col] = make_float2(o2, o3);
    }
}

#define SMEM_NS1 (((TILE + 6) * RST + 3 * 2 * 2048 + 256 + 384) * 4)
#define SMEM_NS2 (((2 * TILE + 12) * RST + 3 * 1 * 2048 + 256 + 384) * 4)

// ---------------- end: zf = z @ end_k + end_b ----------------
__global__ void end_kernel(const float* __restrict__ z, const float* __restrict__ ek,
                           const float* __restrict__ eb, float* __restrict__ zf, int Tf) {
    int warp = (blockIdx.x * blockDim.x + threadIdx.x) >> 5;
    int lane = threadIdx.x & 31;
    if (warp >= Bz * Tf) return;
    float4 v = ((const float4*)(z + (size_t)warp * C))[lane];
    float4 e = ((const float4*)ek)[lane];
    float s = v.x * e.x + v.y * e.y + v.z * e.z + v.w * e.w;
#pragma unroll
    for (int o = 16; o >= 1; o >>= 1) s += __shfl_xor_sync(0xffffffffu, s, o);
    if (lane == 0) zf[warp] = s + eb[0];
}

// ---------------- final output assembly ----------------
__global__ void final_kernel(const float* __restrict__ foundry, const float* __restrict__ zf,
                             float* __restrict__ out, int out_size, int Tf) {
    int idx = blockIdx.x * blockDim.x + threadIdx.x;
    if (idx >= out_size) return;
    if (idx < Bz * S0) {
        int b = idx >> 13, t = idx & (S0 - 1);
        out[idx] = (t < S0 - 1) ? foundry[(b << 13) + t + 1] : zf[b * Tf + (Tf - 1)];
    } else if (idx < Bz * S0 + Bz * Tf) {
        out[idx] = zf[idx - Bz * S0];
    } else {
        out[idx] = 0.0f;
    }
}

extern "C" void kernel_launch(void* const* d_in, const int* in_sizes, int n_in,
                              void* d_out, int out_size) {
    const float* foundry = (const float*)d_in[0];
    const float* ipt     = (const float*)d_in[1];
    const float* start_k = (const float*)d_in[2];
    const float* start_b = (const float*)d_in[3];
    const float* w_dyn   = (const float*)d_in[4];
    const float* ln_s    = (const float*)d_in[5];
    const float* ln_b    = (const float*)d_in[6];
    const float* pw_k    = (const float*)d_in[7];
    const float* pw_b    = (const float*)d_in[8];
    const float* end_k   = (const float*)d_in[9];
    const float* end_b   = (const float*)d_in[10];
    float* out = (float*)d_out;

    float *pA, *pB, *pZ;
    unsigned *pW, *pP;
    cudaGetSymbolAddress((void**)&pA, g_bufA);
    cudaGetSymbolAddress((void**)&pB, g_bufB);
    cudaGetSymbolAddress((void**)&pW, g_whl);
    cudaGetSymbolAddress((void**)&pP, g_phl);
    cudaGetSymbolAddress((void**)&pZ, g_zf);

    cudaFuncSetAttribute(conv_tpl<1>, cudaFuncAttributeMaxDynamicSharedMemorySize, SMEM_NS1);
    cudaFuncSetAttribute(conv_tpl<2>, cudaFuncAttributeMaxDynamicSharedMemorySize, SMEM_NS2);

    split_wd_kernel<<<(DEPTH * Kc * 8 * 128 * 4 + 255) / 256, 256>>>(w_dyn, (uint4*)pW);
    split_pk_kernel<<<(DEPTH * 8 * 128 * 4 + 255) / 256, 256>>>(pw_k, (uint4*)pP);
    start_kernel<<<(Bz * S0 * C) / 256, 256>>>(ipt, start_k, start_b, pA);

    // block 0: stride-2 target block, 8192 -> 4090
    int T = S0;
    int T2 = (S0 - 2 * Kc) / 2 + 1;   // 4090
    conv_tpl<2><<<dim3((T2 + TILE - 1) / TILE, Bz), 256, SMEM_NS2>>>(
        pA, pB, T, T2, pW, ln_s, ln_b, pP, pw_b);

    float* src = pB;
    float* dst = pA;
    int Tc = T2;
    for (int i = 1; i < DEPTH; i++) {
        int To = Tc - (Kc - 1);
        conv_tpl<1><<<dim3((To + TILE - 1) / TILE, Bz), 256, SMEM_NS1>>>(
            src, dst, Tc, To,
            pW + (size_t)i * Kc * 8 * 128 * 16,
            ln_s + i * C, ln_b + i * C,
            pP + (size_t)i * 8 * 128 * 16, pw_b + i * C);
        float* tmp = src; src = dst; dst = tmp;
        Tc = To;
    }

    int warps = Bz * Tc;
    end_kernel<<<(warps * 32 + 255) / 256, 256>>>(src, end_k, end_b, pZ, Tc);
    final_kernel<<<(out_size + 255) / 256, 256>>>(foundry, pZ, out, out_size, Tc);
}

// round 16
// speedup vs baseline: 1.2004x; 1.2004x over previous
#include <cuda_runtime.h>
#include <math.h>
#include <stdint.h>

#define C 128
#define Kc 7
#define TILE 64
#define RST 136            // xs row stride in u32 (136 mod 32 == 8 -> conflict-free)
#define DEPTH 16
#define Bz 4
#define S0 8192

// ---------------- scratch (no allocs allowed) ----------------
__device__ float g_bufA[Bz * S0 * C];
__device__ float g_bufB[Bz * S0 * C];
// dyn weights, MMA-native: [i][k][half(0..7)][d(0..127)][g(0..3)][4 u32: bh0,bh1,bl0,bl1]
__device__ unsigned g_whl[DEPTH * Kc * 8 * 128 * 16];
// pointwise, same per-half layout: [i][half][d][g][4]
__device__ unsigned g_phl[DEPTH * 8 * 128 * 16];
__device__ float g_zf[Bz * 4000];

// round-6/7 proven numerics (measured rel_err 3.02e-4 over full net)
__device__ __forceinline__ float fast_tanh(float x) {
    return __fdividef(2.0f, 1.0f + __expf(-2.0f * x)) - 1.0f;
}
__device__ __forceinline__ float gelu_t(float x) {
    float u = 0.7978845608028654f * (x + 0.044715f * x * x * x);
    return __fdividef(x, 1.0f + __expf(-2.0f * u));
}
// pack two floats to bf16x2: low 16 bits = x0, high = x1
__device__ __forceinline__ unsigned pk2(float x0, float x1) {
    unsigned r; asm("cvt.rn.bf16x2.f32 %0, %1, %2;" : "=r"(r) : "f"(x1), "f"(x0)); return r;
}
__device__ __forceinline__ float bf_lo(unsigned u) { return __uint_as_float(u << 16); }
__device__ __forceinline__ float bf_hi(unsigned u) { return __uint_as_float(u & 0xffff0000u); }

#define MMA16(d, a, b0v, b1v) asm volatile( \
    "mma.sync.aligned.m16n8k16.row.col.f32.bf16.bf16.f32 " \
    "{%0,%1,%2,%3},{%4,%5,%6,%7},{%8,%9},{%0,%1,%2,%3};" \
    : "+f"(d[0]), "+f"(d[1]), "+f"(d[2]), "+f"(d[3]) \
    : "r"(a[0]), "r"(a[1]), "r"(a[2]), "r"(a[3]), "r"(b0v), "r"(b1v))

// ---------------- prep (merged): dyn + pointwise weights -> bf16 hi/lo MMA layout ----------------
#define NWD (DEPTH * Kc * 8 * 128 * 4)
#define NPK (DEPTH * 8 * 128 * 4)
__global__ void split_all_kernel(const float* __restrict__ w, const float* __restrict__ p,
                                 uint4* __restrict__ ow, uint4* __restrict__ op) {
    int idx = blockIdx.x * blockDim.x + threadIdx.x;
    if (idx < NWD) {
        int g = idx & 3;
        int d = (idx >> 2) & 127;
        int half = (idx >> 9) & 7;
        int rest = idx >> 12;
        int k = rest % Kc;
        int i = rest / Kc;
        int c0 = half * 16 + 2 * g;
        const float* wb = w + ((size_t)(i * C + d) * C) * Kc + k;
        float v0 = __ldg(wb + (size_t)c0 * Kc),       v1 = __ldg(wb + (size_t)(c0 + 1) * Kc);
        float v8 = __ldg(wb + (size_t)(c0 + 8) * Kc), v9 = __ldg(wb + (size_t)(c0 + 9) * Kc);
        unsigned h0 = pk2(v0, v1), h1 = pk2(v8, v9);
        unsigned l0 = pk2(v0 - bf_lo(h0), v1 - bf_hi(h0));
        unsigned l1 = pk2(v8 - bf_lo(h1), v9 - bf_hi(h1));
        ow[idx] = make_uint4(h0, h1, l0, l1);
    } else if (idx < NWD + NPK) {
        int j = idx - NWD;
        int g = j & 3;
        int d = (j >> 2) & 127;
        int half = (j >> 9) & 7;
        int i = j >> 12;
        int c0 = half * 16 + 2 * g;
        const float* pb = p + (size_t)i * C * C + d;
        float v0 = __ldg(pb + (size_t)c0 * C),       v1 = __ldg(pb + (size_t)(c0 + 1) * C);
        float v8 = __ldg(pb + (size_t)(c0 + 8) * C), v9 = __ldg(pb + (size_t)(c0 + 9) * C);
        unsigned h0 = pk2(v0, v1), h1 = pk2(v8, v9);
        unsigned l0 = pk2(v0 - bf_lo(h0), v1 - bf_hi(h0));
        unsigned l1 = pk2(v8 - bf_lo(h1), v9 - bf_hi(h1));
        op[j] = make_uint4(h0, h1, l0, l1);
    }
}

// ---------------- start: z = gelu(ipt @ start_k + start_b) ----------------
__global__ void start_kernel(const float* __restrict__ ipt, const float* __restrict__ sk,
                             const float* __restrict__ sb, float* __restrict__ z) {
    int idx = blockIdx.x * blockDim.x + threadIdx.x;
    int c = idx & (C - 1);
    int bt = idx >> 7;
    z[idx] = gelu_t(ipt[bt] * sk[c] + sb[c]);
}

// ---------------- fused conv block, bf16x3 tensor cores (round-6 measured optimum) ----------------
// 256 threads = 8 warps: wm = wid&3 -> m16 tile rows [16wm,16wm+16), wn = wid>>2 -> n cols
// [64wn,64wn+64). x in smem ONLY as packed bf16 {hi,lo} pairs: xs[row][c2][2] u32, stride
// RST=136. Weights stream through cp.async double buffer in MMA-native uint4 layout
// (one LDS.128 = all 4 B regs). 3 bf16 MMAs (hh, hl, lh) ~ fp32 accuracy.
template <int NS>
__global__ __launch_bounds__(256, 2) void conv_tpl(
    const float* __restrict__ xin, float* __restrict__ xout,
    int T_in, int T_out,
    const unsigned* __restrict__ wsp,   // layer's [Kc][8][128][16] u32
    const float* __restrict__ ls, const float* __restrict__ lb,
    const unsigned* __restrict__ pks,   // layer's [8][128][16] u32
    const float* __restrict__ pb) {
    constexpr int XROWS = (NS == 1) ? (TILE + 6) : (2 * TILE + 12);
    constexpr int CPB   = (NS == 1) ? 64 : 32;        // channels per chunk
    constexpr int HPC   = CPB / 16;                   // 16-chan halves per chunk (4 / 2)
    constexpr int NCPP  = C / CPB;                    // chunks per pass (2 / 4)
    constexpr int NWCH  = NS * Kc * NCPP;             // 14 / 56
    constexpr int NCH   = NWCH + NCPP;
    constexpr int WBF   = HPC * 2048;                 // u32 per buffer
    constexpr int NCPA  = HPC * 2;                    // 16B cp.asyncs per thread

    extern __shared__ unsigned smu[];
    unsigned* xs   = smu;                    // XROWS * RST (rows 0..63 reused for LN output)
    unsigned* wbuf = smu + XROWS * RST;      // 2 * WBF
    float* lnS = (float*)(wbuf + 2 * WBF);   // [2][64]
    float* lnQ = lnS + 128;
    float* prm = lnQ + 128;                  // ls | lb | pb

    const int b  = blockIdx.y;
    const int t0 = blockIdx.x * TILE;
    const float* xb = xin + (size_t)b * T_in * C;
    float* ob = xout + (size_t)b * T_out * C;

    const int tid  = threadIdx.x;
    const int lane = tid & 31;
    const int wid  = tid >> 5;
    const int wm   = wid & 3;
    const int wn   = wid >> 2;
    const int gr   = lane >> 2;
    const int gq   = lane & 3;

    if (tid < 128) { prm[tid] = ls[tid]; prm[128 + tid] = lb[tid]; prm[256 + tid] = pb[tid]; }

    // load x rows, convert+pack bf16 hi/lo: one float4 -> uint4 {h0,l0,h1,l1}
    for (int i = tid; i < XROWS * 32; i += 256) {
        int r = i >> 5, c4 = i & 31;
        int rr = min(NS * t0 + r, T_in - 1);
        float4 v = ((const float4*)(xb + (size_t)rr * C))[c4];
        unsigned h0 = pk2(v.x, v.y);
        unsigned l0 = pk2(v.x - bf_lo(h0), v.y - bf_hi(h0));
        unsigned h1 = pk2(v.z, v.w);
        unsigned l1 = pk2(v.z - bf_lo(h1), v.w - bf_hi(h1));
        *(uint4*)&xs[r * RST + c4 * 4] = make_uint4(h0, l0, h1, l1);
    }

    const int row0 = 16 * wm + gr;   // rows of this thread's m16 fragments
    const int row1 = row0 + 8;

    auto prefetch = [&](int q) {
        const unsigned* src;
        if (q < NWCH) {
            int k  = (NS == 1) ? (q >> 1) : (q >> 3);
            int cp = q & (NCPP - 1);
            src = wsp + (size_t)(k * 8 + cp * HPC) * 2048;
        } else {
            src = pks + (size_t)(q - NWCH) * HPC * 2048;
        }
        unsigned da = (unsigned)__cvta_generic_to_shared(wbuf + (q & 1) * WBF) + tid * 16;
        const unsigned* sp = src + tid * 4;
#pragma unroll
        for (int j = 0; j < NCPA; j++)
            asm volatile("cp.async.cg.shared.global [%0], [%1], 16;"
                         :: "r"(da + j * 4096), "l"(sp + j * 1024));
    };

    float Y[8][4], G[8][4];
#pragma unroll
    for (int j = 0; j < 8; j++) { Y[j][0] = Y[j][1] = Y[j][2] = Y[j][3] = 0.0f; }

    prefetch(0);
    asm volatile("cp.async.commit_group;");

    for (int q = 0; q < NCH; q++) {
        __syncthreads();                     // prev chunk consumed (q==0: xs/prm stores done)
        if (q + 1 < NCH) prefetch(q + 1);
        asm volatile("cp.async.commit_group;");
        asm volatile("cp.async.wait_group 1;");
        __syncthreads();                     // chunk q resident

        const unsigned* wb = wbuf + (q & 1) * WBF;
        const bool wphase = (q < NWCH);
        int k = 0, s = 0, cp, arow0;
        if (wphase) {
            cp = q & (NCPP - 1);
            if (NS == 1) { k = q >> 1; arow0 = row0 + 6; }
            else { k = q >> 3; s = (q >> 2) & 1; arow0 = 2 * row0 + 12 + s; }
            if (cp == 0) {
#pragma unroll
                for (int j = 0; j < 8; j++) { G[j][0] = G[j][1] = G[j][2] = G[j][3] = 0.0f; }
            }
        } else {
            cp = q - NWCH;
            arow0 = row0;
            if (q == NWCH) {
#pragma unroll
                for (int j = 0; j < 8; j++) { G[j][0] = G[j][1] = G[j][2] = G[j][3] = 0.0f; }
            }
        }
        const int arow1 = arow0 + ((wphase && NS == 2) ? 16 : 8);
        const int hb0 = cp * HPC;            // global 16-chan half base

#pragma unroll
        for (int h = 0; h < HPC; h++) {
            int c2b = (hb0 + h) * 8;         // c2 base of this 16-chan half
            // A fragments: 4 LDS.64 -> {hi,lo} each
            uint2 p0 = *(const uint2*)&xs[arow0 * RST + (c2b + gq) * 2];
            uint2 p1 = *(const uint2*)&xs[arow1 * RST + (c2b + gq) * 2];
            uint2 p2 = *(const uint2*)&xs[arow0 * RST + (c2b + gq + 4) * 2];
            uint2 p3 = *(const uint2*)&xs[arow1 * RST + (c2b + gq + 4) * 2];
            unsigned ah[4] = { p0.x, p1.x, p2.x, p3.x };
            unsigned al[4] = { p0.y, p1.y, p2.y, p3.y };
            const unsigned* wh = wb + h * 2048;
#pragma unroll
            for (int j = 0; j < 8; j++) {
                int dc = wn * 64 + j * 8 + gr;
                uint4 bv = *(const uint4*)(wh + dc * 16 + gq * 4);  // bh0,bh1,bl0,bl1
                MMA16(G[j], ah, bv.x, bv.y);
                MMA16(G[j], ah, bv.z, bv.w);
                MMA16(G[j], al, bv.x, bv.y);
            }
        }

        if (wphase && cp == NCPP - 1) {
            // fold tap (k[,s]): Y += x[tap,d] * tanh(G)
            int f0 = (NS == 1) ? (row0 + k) : (2 * row0 + 2 * k + s);
            int f1 = (NS == 1) ? (f0 + 8) : (f0 + 16);
#pragma unroll
            for (int j = 0; j < 8; j++) {
                int c2 = wn * 32 + j * 4 + gq;
                uint2 u0 = *(const uint2*)&xs[f0 * RST + c2 * 2];
                uint2 u1 = *(const uint2*)&xs[f1 * RST + c2 * 2];
                Y[j][0] += (bf_lo(u0.x) + bf_lo(u0.y)) * fast_tanh(G[j][0]);
                Y[j][1] += (bf_hi(u0.x) + bf_hi(u0.y)) * fast_tanh(G[j][1]);
                Y[j][2] += (bf_lo(u1.x) + bf_lo(u1.y)) * fast_tanh(G[j][2]);
                Y[j][3] += (bf_hi(u1.x) + bf_hi(u1.y)) * fast_tanh(G[j][3]);
            }
            if (q == NWCH - 1) {
                // residual + layernorm; inner barrier orders all xs reads before rewrite
                int r0 = (NS == 1) ? (row0 + 6) : (2 * row0 + 12);
                int r1 = (NS == 1) ? (r0 + 8) : (r0 + 16);
                float s0 = 0, q0 = 0, s1 = 0, q1 = 0;
#pragma unroll
                for (int j = 0; j < 8; j++) {
                    int c2 = wn * 32 + j * 4 + gq;
                    uint2 u0 = *(const uint2*)&xs[r0 * RST + c2 * 2];
                    uint2 u1 = *(const uint2*)&xs[r1 * RST + c2 * 2];
                    Y[j][0] += bf_lo(u0.x) + bf_lo(u0.y);
                    Y[j][1] += bf_hi(u0.x) + bf_hi(u0.y);
                    Y[j][2] += bf_lo(u1.x) + bf_lo(u1.y);
                    Y[j][3] += bf_hi(u1.x) + bf_hi(u1.y);
                    s0 += Y[j][0] + Y[j][1]; q0 += Y[j][0] * Y[j][0] + Y[j][1] * Y[j][1];
                    s1 += Y[j][2] + Y[j][3]; q1 += Y[j][2] * Y[j][2] + Y[j][3] * Y[j][3];
                }
#pragma unroll
                for (int o = 1; o <= 2; o <<= 1) {
                    s0 += __shfl_xor_sync(0xffffffffu, s0, o);
                    q0 += __shfl_xor_sync(0xffffffffu, q0, o);
                    s1 += __shfl_xor_sync(0xffffffffu, s1, o);
                    q1 += __shfl_xor_sync(0xffffffffu, q1, o);
                }
                if (gq == 0) {
                    lnS[wn * 64 + row0] = s0; lnQ[wn * 64 + row0] = q0;
                    lnS[wn * 64 + row1] = s1; lnQ[wn * 64 + row1] = q1;
                }
                __syncthreads();
                float Sa = lnS[row0] + lnS[64 + row0], Qa = lnQ[row0] + lnQ[64 + row0];
                float Sb = lnS[row1] + lnS[64 + row1], Qb = lnQ[row1] + lnQ[64 + row1];
                float m0 = Sa * (1.0f / C), m1 = Sb * (1.0f / C);
                float i0 = rsqrtf(fmaxf(Qa * (1.0f / C) - m0 * m0, 0.0f) + 1e-6f);
                float i1 = rsqrtf(fmaxf(Qb * (1.0f / C) - m1 * m1, 0.0f) + 1e-6f);
#pragma unroll
                for (int j = 0; j < 8; j++) {
                    int col = wn * 64 + j * 8 + gq * 2;
                    Y[j][0] = (Y[j][0] - m0) * i0 * prm[col]     + prm[128 + col];
                    Y[j][1] = (Y[j][1] - m0) * i0 * prm[col + 1] + prm[128 + col + 1];
                    Y[j][2] = (Y[j][2] - m1) * i1 * prm[col]     + prm[128 + col];
                    Y[j][3] = (Y[j][3] - m1) * i1 * prm[col + 1] + prm[128 + col + 1];
                    int c2 = col >> 1;
                    unsigned h0 = pk2(Y[j][0], Y[j][1]);
                    unsigned l0 = pk2(Y[j][0] - bf_lo(h0), Y[j][1] - bf_hi(h0));
                    unsigned h1 = pk2(Y[j][2], Y[j][3]);
                    unsigned l1 = pk2(Y[j][2] - bf_lo(h1), Y[j][3] - bf_hi(h1));
                    *(uint2*)&xs[row0 * RST + c2 * 2] = make_uint2(h0, l0);
                    *(uint2*)&xs[row1 * RST + c2 * 2] = make_uint2(h1, l1);
                }
                // loop-top __syncthreads publishes LN rows before pointwise A-loads
            }
        }
    }

    // epilogue: out = y_ln + gelu(G + pb)
#pragma unroll
    for (int j = 0; j < 8; j++) {
        int col = wn * 64 + j * 8 + gq * 2;
        int tg0 = t0 + row0, tg1 = t0 + row1;
        float o0 = Y[j][0] + gelu_t(G[j][0] + prm[256 + col]);
        float o1 = Y[j][1] + gelu_t(G[j][1] + prm[256 + col + 1]);
        float o2 = Y[j][2] + gelu_t(G[j][2] + prm[256 + col]);
        float o3 = Y[j][3] + gelu_t(G[j][3] + prm[256 + col + 1]);
        if (tg0 < T_out) *(float2*)&ob[(size_t)tg0 * C + col] = make_float2(o0, o1);
        if (tg1 < T_out) *(float2*)&ob[(size_t)tg1 * C + col] = make_float2(o2, o3);
    }
}

#define SMEM_NS1 (((TILE + 6) * RST + 2 * 4 * 2048 + 256 + 384) * 4)
#define SMEM_NS2 (((2 * TILE + 12) * RST + 2 * 2 * 2048 + 256 + 384) * 4)

// ---------------- end: zf = z @ end_k + end_b ----------------
__global__ void end_kernel(const float* __restrict__ z, const float* __restrict__ ek,
                           const float* __restrict__ eb, float* __restrict__ zf, int Tf) {
    int warp = (blockIdx.x * blockDim.x + threadIdx.x) >> 5;
    int lane = threadIdx.x & 31;
    if (warp >= Bz * Tf) return;
    float4 v = ((const float4*)(z + (size_t)warp * C))[lane];
    float4 e = ((const float4*)ek)[lane];
    float s = v.x * e.x + v.y * e.y + v.z * e.z + v.w * e.w;
#pragma unroll
    for (int o = 16; o >= 1; o >>= 1) s += __shfl_xor_sync(0xffffffffu, s, o);
    if (lane == 0) zf[warp] = s + eb[0];
}

// ---------------- final output assembly ----------------
__global__ void final_kernel(const float* __restrict__ foundry, const float* __restrict__ zf,
                             float* __restrict__ out, int out_size, int Tf) {
    int idx = blockIdx.x * blockDim.x + threadIdx.x;
    if (idx >= out_size) return;
    if (idx < Bz * S0) {
        int b = idx >> 13, t = idx & (S0 - 1);
        out[idx] = (t < S0 - 1) ? foundry[(b << 13) + t + 1] : zf[b * Tf + (Tf - 1)];
    } else if (idx < Bz * S0 + Bz * Tf) {
        out[idx] = zf[idx - Bz * S0];
    } else {
        out[idx] = 0.0f;
    }
}

extern "C" void kernel_launch(void* const* d_in, const int* in_sizes, int n_in,
                              void* d_out, int out_size) {
    const float* foundry = (const float*)d_in[0];
    const float* ipt     = (const float*)d_in[1];
    const float* start_k = (const float*)d_in[2];
    const float* start_b = (const float*)d_in[3];
    const float* w_dyn   = (const float*)d_in[4];
    const float* ln_s    = (const float*)d_in[5];
    const float* ln_b    = (const float*)d_in[6];
    const float* pw_k    = (const float*)d_in[7];
    const float* pw_b    = (const float*)d_in[8];
    const float* end_k   = (const float*)d_in[9];
    const float* end_b   = (const float*)d_in[10];
    float* out = (float*)d_out;

    float *pA, *pB, *pZ;
    unsigned *pW, *pP;
    cudaGetSymbolAddress((void**)&pA, g_bufA);
    cudaGetSymbolAddress((void**)&pB, g_bufB);
    cudaGetSymbolAddress((void**)&pW, g_whl);
    cudaGetSymbolAddress((void**)&pP, g_phl);
    cudaGetSymbolAddress((void**)&pZ, g_zf);

    cudaFuncSetAttribute(conv_tpl<1>, cudaFuncAttributeMaxDynamicSharedMemorySize, SMEM_NS1);
    cudaFuncSetAttribute(conv_tpl<2>, cudaFuncAttributeMaxDynamicSharedMemorySize, SMEM_NS2);

    split_all_kernel<<<(NWD + NPK + 511) / 512, 512>>>(w_dyn, pw_k, (uint4*)pW, (uint4*)pP);
    start_kernel<<<(Bz * S0 * C) / 256, 256>>>(ipt, start_k, start_b, pA);

    // block 0: stride-2 target block, 8192 -> 4090
    int T = S0;
    int T2 = (S0 - 2 * Kc) / 2 + 1;   // 4090
    conv_tpl<2><<<dim3((T2 + TILE - 1) / TILE, Bz), 256, SMEM_NS2>>>(
        pA, pB, T, T2, pW, ln_s, ln_b, pP, pw_b);

    float* src = pB;
    float* dst = pA;
    int Tc = T2;
    for (int i = 1; i < DEPTH; i++) {
        int To = Tc - (Kc - 1);
        conv_tpl<1><<<dim3((To + TILE - 1) / TILE, Bz), 256, SMEM_NS1>>>(
            src, dst, Tc, To,
            pW + (size_t)i * Kc * 8 * 128 * 16,
            ln_s + i * C, ln_b + i * C,
            pP + (size_t)i * 8 * 128 * 16, pw_b + i * C);
        float* tmp = src; src = dst; dst = tmp;
        Tc = To;
    }

    int warps = Bz * Tc;
    end_kernel<<<(warps * 32 + 255) / 256, 256>>>(src, end_k, end_b, pZ, Tc);
    final_kernel<<<(out_size + 255) / 256, 256>>>(foundry, pZ, out, out_size, Tc);
}